// round 3
// baseline (speedup 1.0000x reference)
#include <cuda_runtime.h>

// Problem constants
#define NB 4
#define NT 2048
#define ND 1024
#define NH 16
#define NHD 64
#define NM (NB * NT)  // 8192

// Scratch: q/k/v in (B,H,T,HD) layout, ctx in (B,T,H,HD) = (M, D) layout.
__device__ float g_q[NB * NH * NT * NHD];
__device__ float g_k[NB * NH * NT * NHD];
__device__ float g_v[NB * NH * NT * NHD];
__device__ float g_ctx[NM * ND];

// ---------------------------------------------------------------------------
// Kernel 1: fused QKV projection.
// Out[b,h,t,e] = sum_d X[b,t,d] * W[h,d,e]; M=8192, N=64, K=1024.
// Tile 64x64x16, 256 threads, 4x4 micro-tile per thread.
// ---------------------------------------------------------------------------
__global__ __launch_bounds__(256)
void qkv_proj_kernel(const float* __restrict__ X,
                     const float* __restrict__ Wq,
                     const float* __restrict__ Wk,
                     const float* __restrict__ Wv)
{
    __shared__ float AsT[16][64];
    __shared__ float Bs[16][64];

    const int zz  = blockIdx.y;
    const int mat = zz >> 4;    // 0=q, 1=k, 2=v
    const int h   = zz & 15;

    const float* W;
    float* Out;
    if (mat == 0)      { W = Wq; Out = g_q; }
    else if (mat == 1) { W = Wk; Out = g_k; }
    else               { W = Wv; Out = g_v; }
    W += (size_t)h * ND * NHD;

    const int m0 = blockIdx.x * 64;
    const int t  = threadIdx.x;
    const int tx = t & 15, ty = t >> 4;
    const int r  = t >> 2, c  = t & 3;

    float acc[4][4] = {};

    for (int k0 = 0; k0 < ND; k0 += 16) {
        float4 av = *(const float4*)(X + (size_t)(m0 + r) * ND + k0 + 4 * c);
        AsT[4 * c + 0][r] = av.x;
        AsT[4 * c + 1][r] = av.y;
        AsT[4 * c + 2][r] = av.z;
        AsT[4 * c + 3][r] = av.w;
        *(float4*)&Bs[ty][4 * tx] =
            *(const float4*)(W + (size_t)(k0 + ty) * NHD + 4 * tx);
        __syncthreads();

#pragma unroll
        for (int kk = 0; kk < 16; kk++) {
            float4 a = *(const float4*)&AsT[kk][4 * ty];
            float4 b = *(const float4*)&Bs[kk][4 * tx];
            float aa[4] = {a.x, a.y, a.z, a.w};
            float bb[4] = {b.x, b.y, b.z, b.w};
#pragma unroll
            for (int i = 0; i < 4; i++)
#pragma unroll
                for (int j = 0; j < 4; j++)
                    acc[i][j] += aa[i] * bb[j];
        }
        __syncthreads();
    }

#pragma unroll
    for (int i = 0; i < 4; i++) {
        int m   = m0 + 4 * ty + i;
        int bb_ = m >> 11;          // / NT
        int tt_ = m & (NT - 1);     // % NT
        float4 o = make_float4(acc[i][0], acc[i][1], acc[i][2], acc[i][3]);
        *(float4*)(Out + ((size_t)(bb_ * NH + h) * NT + tt_) * NHD + 4 * tx) = o;
    }
}

// ---------------------------------------------------------------------------
// Kernel 2: causal flash attention, fp32, BM=BN=64, 256 threads.
// Q/K tiles stored e-major (transposed). FIX vs R1: the transposed Q and K
// loads now cover the FULL 64x64 tile (4 e-chunks of 16), not just e=0..15.
// ---------------------------------------------------------------------------
__global__ __launch_bounds__(256)
void attn_kernel()
{
    __shared__ float QsT[64][64];  // QsT[e][row]
    __shared__ float KP[64][64];   // KsT[e][col] during S; P[row][col] during PV
    __shared__ float Vs[64][64];   // Vs[col][e]

    const int bh = blockIdx.y;
    const int qb = (NT / 64 - 1) - blockIdx.x;  // heavy blocks first
    const float* Qp = g_q + (size_t)bh * NT * NHD;
    const float* Kp = g_k + (size_t)bh * NT * NHD;
    const float* Vp = g_v + (size_t)bh * NT * NHD;

    const int t  = threadIdx.x;
    const int tx = t & 15, ty = t >> 4;
    const int r  = t >> 2, c  = t & 3;

    // Load Q tile transposed: full 64 rows x 64 e-dims
#pragma unroll
    for (int w = 0; w < 4; w++) {
        float4 qv = *(const float4*)(Qp + (size_t)(qb * 64 + r) * NHD + 16 * w + 4 * c);
        QsT[16 * w + 4 * c + 0][r] = qv.x;
        QsT[16 * w + 4 * c + 1][r] = qv.y;
        QsT[16 * w + 4 * c + 2][r] = qv.z;
        QsT[16 * w + 4 * c + 3][r] = qv.w;
    }

    float Oacc[4][4] = {};
    float mrow[4] = {-1e30f, -1e30f, -1e30f, -1e30f};
    float lrow[4] = {};

    for (int kb = 0; kb <= qb; kb++) {
        __syncthreads();  // Q load (iter 0) / previous PV reads done

        // K tile transposed: full 64x64
#pragma unroll
        for (int w = 0; w < 4; w++) {
            float4 kv = *(const float4*)(Kp + (size_t)(kb * 64 + r) * NHD + 16 * w + 4 * c);
            KP[16 * w + 4 * c + 0][r] = kv.x;
            KP[16 * w + 4 * c + 1][r] = kv.y;
            KP[16 * w + 4 * c + 2][r] = kv.z;
            KP[16 * w + 4 * c + 3][r] = kv.w;
        }
        // V tile, natural layout
#pragma unroll
        for (int w = 0; w < 4; w++) {
            int idx = (w << 8) + t;
            int jr = idx >> 4, c4 = idx & 15;
            *(float4*)&Vs[jr][4 * c4] =
                *(const float4*)(Vp + (size_t)(kb * 64 + jr) * NHD + 4 * c4);
        }
        __syncthreads();

        // S = Q @ K^T (over e)
        float S[4][4] = {};
#pragma unroll 4
        for (int e = 0; e < 64; e++) {
            float4 a = *(const float4*)&QsT[e][4 * ty];
            float4 b = *(const float4*)&KP[e][4 * tx];
            float aa[4] = {a.x, a.y, a.z, a.w};
            float bb[4] = {b.x, b.y, b.z, b.w};
#pragma unroll
            for (int i = 0; i < 4; i++)
#pragma unroll
                for (int j = 0; j < 4; j++)
                    S[i][j] += aa[i] * bb[j];
        }

        // scale by 1/sqrt(D) = 1/32; causal mask only on diagonal block
        const float sc = 0.03125f;
        if (kb == qb) {
#pragma unroll
            for (int i = 0; i < 4; i++)
#pragma unroll
                for (int j = 0; j < 4; j++) {
                    S[i][j] *= sc;
                    if (4 * tx + j > 4 * ty + i) S[i][j] = -1e30f;
                }
        } else {
#pragma unroll
            for (int i = 0; i < 4; i++)
#pragma unroll
                for (int j = 0; j < 4; j++)
                    S[i][j] *= sc;
        }

        // online softmax per row (rows owned by ty group = 16 tx lanes)
        float alpha[4];
#pragma unroll
        for (int i = 0; i < 4; i++) {
            float v = fmaxf(fmaxf(S[i][0], S[i][1]), fmaxf(S[i][2], S[i][3]));
#pragma unroll
            for (int off = 1; off < 16; off <<= 1)
                v = fmaxf(v, __shfl_xor_sync(0xffffffffu, v, off));
            float mn = fmaxf(mrow[i], v);
            alpha[i] = __expf(mrow[i] - mn);
            mrow[i] = mn;
            float rs = 0.0f;
#pragma unroll
            for (int j = 0; j < 4; j++) {
                S[i][j] = __expf(S[i][j] - mn);
                rs += S[i][j];
            }
#pragma unroll
            for (int off = 1; off < 16; off <<= 1)
                rs += __shfl_xor_sync(0xffffffffu, rs, off);
            lrow[i] = lrow[i] * alpha[i] + rs;
#pragma unroll
            for (int j = 0; j < 4; j++) Oacc[i][j] *= alpha[i];
        }

        __syncthreads();  // all warps done reading KP as K
        // write P (row-major) into KP buffer
#pragma unroll
        for (int i = 0; i < 4; i++)
            *(float4*)&KP[4 * ty + i][4 * tx] =
                make_float4(S[i][0], S[i][1], S[i][2], S[i][3]);
        __syncthreads();

        // O += P @ V  (over j)
#pragma unroll 4
        for (int j = 0; j < 64; j++) {
            float4 bv = *(const float4*)&Vs[j][4 * tx];
            float bb[4] = {bv.x, bv.y, bv.z, bv.w};
#pragma unroll
            for (int i = 0; i < 4; i++) {
                float a = KP[4 * ty + i][j];
#pragma unroll
                for (int jj = 0; jj < 4; jj++)
                    Oacc[i][jj] += a * bb[jj];
            }
        }
    }

    // epilogue: normalize and write ctx in (B,T,H,HD) layout
    const int b = bh >> 4, h = bh & 15;
#pragma unroll
    for (int i = 0; i < 4; i++) {
        float inv = 1.0f / lrow[i];
        int trow = qb * 64 + 4 * ty + i;
        float4 o = make_float4(Oacc[i][0] * inv, Oacc[i][1] * inv,
                               Oacc[i][2] * inv, Oacc[i][3] * inv);
        *(float4*)(g_ctx + ((size_t)(b * NT + trow) * NH + h) * NHD + 4 * tx) = o;
    }
}

// ---------------------------------------------------------------------------
// Kernel 3: output projection. Out[m,n] = sum_k ctx[m,k] * Wo[n,k] + bo[n]
// NT-GEMM: M=8192, N=1024, K=1024. Tile 64x64x16.
// ---------------------------------------------------------------------------
__global__ __launch_bounds__(256)
void out_proj_kernel(const float* __restrict__ Wo,
                     const float* __restrict__ bo,
                     float* __restrict__ Out)
{
    __shared__ float AsT[16][64];
    __shared__ float BsT[16][64];

    const int m0 = blockIdx.x * 64;
    const int n0 = blockIdx.y * 64;
    const int t  = threadIdx.x;
    const int tx = t & 15, ty = t >> 4;
    const int r  = t >> 2, c  = t & 3;

    float acc[4][4] = {};

    for (int k0 = 0; k0 < ND; k0 += 16) {
        float4 av = *(const float4*)(g_ctx + (size_t)(m0 + r) * ND + k0 + 4 * c);
        AsT[4 * c + 0][r] = av.x;
        AsT[4 * c + 1][r] = av.y;
        AsT[4 * c + 2][r] = av.z;
        AsT[4 * c + 3][r] = av.w;
        float4 bv = *(const float4*)(Wo + (size_t)(n0 + r) * ND + k0 + 4 * c);
        BsT[4 * c + 0][r] = bv.x;
        BsT[4 * c + 1][r] = bv.y;
        BsT[4 * c + 2][r] = bv.z;
        BsT[4 * c + 3][r] = bv.w;
        __syncthreads();

#pragma unroll
        for (int kk = 0; kk < 16; kk++) {
            float4 a = *(const float4*)&AsT[kk][4 * ty];
            float4 b = *(const float4*)&BsT[kk][4 * tx];
            float aa[4] = {a.x, a.y, a.z, a.w};
            float bb[4] = {b.x, b.y, b.z, b.w};
#pragma unroll
            for (int i = 0; i < 4; i++)
#pragma unroll
                for (int j = 0; j < 4; j++)
                    acc[i][j] += aa[i] * bb[j];
        }
        __syncthreads();
    }

    float4 bias = *(const float4*)(bo + n0 + 4 * tx);
    float bb[4] = {bias.x, bias.y, bias.z, bias.w};
#pragma unroll
    for (int i = 0; i < 4; i++) {
        float4 o = make_float4(acc[i][0] + bb[0], acc[i][1] + bb[1],
                               acc[i][2] + bb[2], acc[i][3] + bb[3]);
        *(float4*)(Out + (size_t)(m0 + 4 * ty + i) * ND + n0 + 4 * tx) = o;
    }
}

// ---------------------------------------------------------------------------
extern "C" void kernel_launch(void* const* d_in, const int* in_sizes, int n_in,
                              void* d_out, int out_size)
{
    const float* X  = (const float*)d_in[0];
    const float* Wq = (const float*)d_in[1];
    const float* Wk = (const float*)d_in[2];
    const float* Wv = (const float*)d_in[3];
    const float* Wo = (const float*)d_in[4];
    const float* bo = (const float*)d_in[5];
    float* Out = (float*)d_out;

    qkv_proj_kernel<<<dim3(NM / 64, 3 * NH), 256>>>(X, Wq, Wk, Wv);
    attn_kernel<<<dim3(NT / 64, NB * NH), 256>>>();
    out_proj_kernel<<<dim3(NM / 64, ND / 64), 256>>>(Wo, bo, Out);
}

// round 12
// speedup vs baseline: 1.4881x; 1.4881x over previous
#include <cuda_runtime.h>
#include <cuda_bf16.h>
#include <cstdint>

#define NB 4
#define NT 2048
#define ND 1024
#define NH 16
#define NHD 64
#define NM (NB * NT)  // 8192

// ---------------------------------------------------------------------------
// Device scratch (no cudaMalloc anywhere)
// ---------------------------------------------------------------------------
__device__ float g_q[NB * NH * NT * NHD];
__device__ float g_k[NB * NH * NT * NHD];
__device__ float g_v[NB * NH * NT * NHD];
__device__ __nv_bfloat16 g_xh[NM * ND], g_xl[NM * ND];                 // X split
__device__ __nv_bfloat16 g_wth[3 * NH * NHD * ND], g_wtl[3 * NH * NHD * ND]; // W^T split [mat][h][n][k]
__device__ __nv_bfloat16 g_woh[ND * ND], g_wol[ND * ND];               // Wo split [n][k]
__device__ __nv_bfloat16 g_ctxh[NM * ND], g_ctxl[NM * ND];             // ctx split

static __device__ __forceinline__ void split1(float v, __nv_bfloat16& h, __nv_bfloat16& l) {
    h = __float2bfloat16(v);
    l = __float2bfloat16(v - __bfloat162float(h));
}

// m16n8k16 row.col bf16 MMA, fp32 accumulate (baseline PTX, compiles at compute_103)
static __device__ __forceinline__ void mma16816(float* d, const uint32_t* a, const uint32_t* b) {
    asm volatile(
        "mma.sync.aligned.m16n8k16.row.col.f32.bf16.bf16.f32 "
        "{%0,%1,%2,%3}, {%4,%5,%6,%7}, {%8,%9}, {%0,%1,%2,%3};\n"
        : "+f"(d[0]), "+f"(d[1]), "+f"(d[2]), "+f"(d[3])
        : "r"(a[0]), "r"(a[1]), "r"(a[2]), "r"(a[3]), "r"(b[0]), "r"(b[1]));
}

// ---------------------------------------------------------------------------
// Prep: elementwise hi/lo split of X and Wo
// ---------------------------------------------------------------------------
__global__ __launch_bounds__(256)
void split_x_kernel(const float* __restrict__ X) {
    int i = blockIdx.x * 256 + threadIdx.x;           // float4 index
    float4 v = ((const float4*)X)[i];
    __nv_bfloat16 h[4], l[4];
    split1(v.x, h[0], l[0]); split1(v.y, h[1], l[1]);
    split1(v.z, h[2], l[2]); split1(v.w, h[3], l[3]);
    ((uint2*)g_xh)[i] = *(uint2*)h;
    ((uint2*)g_xl)[i] = *(uint2*)l;
}
__global__ __launch_bounds__(256)
void split_wo_kernel(const float* __restrict__ Wo) {
    int i = blockIdx.x * 256 + threadIdx.x;
    float4 v = ((const float4*)Wo)[i];
    __nv_bfloat16 h[4], l[4];
    split1(v.x, h[0], l[0]); split1(v.y, h[1], l[1]);
    split1(v.z, h[2], l[2]); split1(v.w, h[3], l[3]);
    ((uint2*)g_woh)[i] = *(uint2*)h;
    ((uint2*)g_wol)[i] = *(uint2*)l;
}

// Prep: transpose-split Wq/Wk/Wv: [h][k][n] -> [mat][h][n][k] hi/lo
__global__ __launch_bounds__(256)
void wsplit_kernel(const float* __restrict__ Wq, const float* __restrict__ Wk,
                   const float* __restrict__ Wv) {
    __shared__ float tile[64][65];
    const int mat = blockIdx.z, h = blockIdx.y, k0 = blockIdx.x * 64;
    const float* W = (mat == 0 ? Wq : mat == 1 ? Wk : Wv) + (size_t)h * ND * NHD;
    const int t = threadIdx.x, n4 = t & 63, r4 = t >> 6;
#pragma unroll
    for (int i = 0; i < 16; i++) {
        int kk = i * 4 + r4;
        tile[kk][n4] = W[(size_t)(k0 + kk) * NHD + n4];
    }
    __syncthreads();
    __nv_bfloat16* oh = g_wth + (((size_t)mat * NH + h) * NHD) * ND;
    __nv_bfloat16* ol = g_wtl + (((size_t)mat * NH + h) * NHD) * ND;
#pragma unroll
    for (int i = 0; i < 16; i++) {
        int n = i * 4 + r4, kk = n4;
        __nv_bfloat16 hv, lv;
        split1(tile[kk][n], hv, lv);
        oh[(size_t)n * ND + k0 + kk] = hv;
        ol[(size_t)n * ND + k0 + kk] = lv;
    }
}

// ---------------------------------------------------------------------------
// Tensor-core GEMM core: 128x64 block tile, BK=32, 8 warps (4m x 2n),
// warp tile 32x32 = 2 m16 tiles x 4 n8 tiles, split-bf16 (hi*hi+hi*lo+lo*hi).
// Smem rows padded to 40 bf16 -> conflict-free fragment LDS.
// ---------------------------------------------------------------------------
#define SM_PAD 40

// QKV projection: A = X split [m][k], B = W^T split [mat][h][n][k].
// grid (NM/128, 3*NH). Writes fp32 q/k/v in (B,H,T,HD).
__global__ __launch_bounds__(256)
void qkv_tc_kernel() {
    __shared__ __nv_bfloat16 As[2][128][SM_PAD];
    __shared__ __nv_bfloat16 Bs[2][64][SM_PAD];

    const int zz = blockIdx.y;
    const int mat = zz >> 4, h = zz & 15;
    const int m0 = blockIdx.x * 128;
    const __nv_bfloat16* Bh = g_wth + (((size_t)mat * NH + h) * NHD) * ND;
    const __nv_bfloat16* Bl = g_wtl + (((size_t)mat * NH + h) * NHD) * ND;
    float* Outbase = (mat == 0 ? g_q : mat == 1 ? g_k : g_v);

    const int tid = threadIdx.x, lane = tid & 31, wid = tid >> 5;
    const int warp_m = wid & 3, warp_n = wid >> 2;
    const int r0 = lane >> 2, c0 = (lane & 3) * 2;

    float acc[2][4][4] = {};

    for (int k0 = 0; k0 < ND; k0 += 32) {
        // A tile 128x32 (hi+lo): 2 threads per row, 16 elems each
        {
            int row = tid >> 1, cb = (tid & 1) * 16;
            size_t g = (size_t)(m0 + row) * ND + k0 + cb;
            *(uint4*)&As[0][row][cb]     = *(const uint4*)(g_xh + g);
            *(uint4*)&As[0][row][cb + 8] = *(const uint4*)(g_xh + g + 8);
            *(uint4*)&As[1][row][cb]     = *(const uint4*)(g_xl + g);
            *(uint4*)&As[1][row][cb + 8] = *(const uint4*)(g_xl + g + 8);
        }
        // B tile 64x32 (hi+lo): 4 threads per row, 8 elems each
        {
            int row = tid >> 2, cb = (tid & 3) * 8;
            size_t g = (size_t)row * ND + k0 + cb;
            *(uint4*)&Bs[0][row][cb] = *(const uint4*)(Bh + g);
            *(uint4*)&Bs[1][row][cb] = *(const uint4*)(Bl + g);
        }
        __syncthreads();

#pragma unroll
        for (int ks = 0; ks < 32; ks += 16) {
            uint32_t afh[2][4], afl[2][4], bfh[4][2], bfl[4][2];
#pragma unroll
            for (int mi = 0; mi < 2; mi++) {
                int mr = warp_m * 32 + mi * 16 + r0;
                afh[mi][0] = *(const uint32_t*)&As[0][mr][ks + c0];
                afh[mi][1] = *(const uint32_t*)&As[0][mr + 8][ks + c0];
                afh[mi][2] = *(const uint32_t*)&As[0][mr][ks + c0 + 8];
                afh[mi][3] = *(const uint32_t*)&As[0][mr + 8][ks + c0 + 8];
                afl[mi][0] = *(const uint32_t*)&As[1][mr][ks + c0];
                afl[mi][1] = *(const uint32_t*)&As[1][mr + 8][ks + c0];
                afl[mi][2] = *(const uint32_t*)&As[1][mr][ks + c0 + 8];
                afl[mi][3] = *(const uint32_t*)&As[1][mr + 8][ks + c0 + 8];
            }
#pragma unroll
            for (int ni = 0; ni < 4; ni++) {
                int nr = warp_n * 32 + ni * 8 + r0;
                bfh[ni][0] = *(const uint32_t*)&Bs[0][nr][ks + c0];
                bfh[ni][1] = *(const uint32_t*)&Bs[0][nr][ks + c0 + 8];
                bfl[ni][0] = *(const uint32_t*)&Bs[1][nr][ks + c0];
                bfl[ni][1] = *(const uint32_t*)&Bs[1][nr][ks + c0 + 8];
            }
#pragma unroll
            for (int mi = 0; mi < 2; mi++)
#pragma unroll
                for (int ni = 0; ni < 4; ni++) {
                    mma16816(acc[mi][ni], afh[mi], bfh[ni]);
                    mma16816(acc[mi][ni], afh[mi], bfl[ni]);
                    mma16816(acc[mi][ni], afl[mi], bfh[ni]);
                }
        }
        __syncthreads();
    }

    // Epilogue: write fp32 q/k/v in (B,H,T,HD)
#pragma unroll
    for (int mi = 0; mi < 2; mi++) {
#pragma unroll
        for (int half = 0; half < 2; half++) {
            int m = m0 + warp_m * 32 + mi * 16 + r0 + half * 8;
            int b = m >> 11, tt = m & (NT - 1);
            float* Out = Outbase + (((size_t)b * NH + h) * NT + tt) * NHD;
#pragma unroll
            for (int ni = 0; ni < 4; ni++) {
                int n = warp_n * 32 + ni * 8 + c0;
                *(float2*)(Out + n) =
                    make_float2(acc[mi][ni][half * 2], acc[mi][ni][half * 2 + 1]);
            }
        }
    }
}

// Output projection: Out[m,n] = sum_k ctx[m,k]*Wo[n,k] + bo[n].
// grid (NM/128, ND/64).
__global__ __launch_bounds__(256)
void out_tc_kernel(const float* __restrict__ bo, float* __restrict__ Out) {
    __shared__ __nv_bfloat16 As[2][128][SM_PAD];
    __shared__ __nv_bfloat16 Bs[2][64][SM_PAD];

    const int m0 = blockIdx.x * 128;
    const int n0 = blockIdx.y * 64;
    const int tid = threadIdx.x, lane = tid & 31, wid = tid >> 5;
    const int warp_m = wid & 3, warp_n = wid >> 2;
    const int r0 = lane >> 2, c0 = (lane & 3) * 2;

    float acc[2][4][4] = {};

    for (int k0 = 0; k0 < ND; k0 += 32) {
        {
            int row = tid >> 1, cb = (tid & 1) * 16;
            size_t g = (size_t)(m0 + row) * ND + k0 + cb;
            *(uint4*)&As[0][row][cb]     = *(const uint4*)(g_ctxh + g);
            *(uint4*)&As[0][row][cb + 8] = *(const uint4*)(g_ctxh + g + 8);
            *(uint4*)&As[1][row][cb]     = *(const uint4*)(g_ctxl + g);
            *(uint4*)&As[1][row][cb + 8] = *(const uint4*)(g_ctxl + g + 8);
        }
        {
            int row = tid >> 2, cb = (tid & 3) * 8;
            size_t g = (size_t)(n0 + row) * ND + k0 + cb;
            *(uint4*)&Bs[0][row][cb] = *(const uint4*)(g_woh + g);
            *(uint4*)&Bs[1][row][cb] = *(const uint4*)(g_wol + g);
        }
        __syncthreads();

#pragma unroll
        for (int ks = 0; ks < 32; ks += 16) {
            uint32_t afh[2][4], afl[2][4], bfh[4][2], bfl[4][2];
#pragma unroll
            for (int mi = 0; mi < 2; mi++) {
                int mr = warp_m * 32 + mi * 16 + r0;
                afh[mi][0] = *(const uint32_t*)&As[0][mr][ks + c0];
                afh[mi][1] = *(const uint32_t*)&As[0][mr + 8][ks + c0];
                afh[mi][2] = *(const uint32_t*)&As[0][mr][ks + c0 + 8];
                afh[mi][3] = *(const uint32_t*)&As[0][mr + 8][ks + c0 + 8];
                afl[mi][0] = *(const uint32_t*)&As[1][mr][ks + c0];
                afl[mi][1] = *(const uint32_t*)&As[1][mr + 8][ks + c0];
                afl[mi][2] = *(const uint32_t*)&As[1][mr][ks + c0 + 8];
                afl[mi][3] = *(const uint32_t*)&As[1][mr + 8][ks + c0 + 8];
            }
#pragma unroll
            for (int ni = 0; ni < 4; ni++) {
                int nr = warp_n * 32 + ni * 8 + r0;
                bfh[ni][0] = *(const uint32_t*)&Bs[0][nr][ks + c0];
                bfh[ni][1] = *(const uint32_t*)&Bs[0][nr][ks + c0 + 8];
                bfl[ni][0] = *(const uint32_t*)&Bs[1][nr][ks + c0];
                bfl[ni][1] = *(const uint32_t*)&Bs[1][nr][ks + c0 + 8];
            }
#pragma unroll
            for (int mi = 0; mi < 2; mi++)
#pragma unroll
                for (int ni = 0; ni < 4; ni++) {
                    mma16816(acc[mi][ni], afh[mi], bfh[ni]);
                    mma16816(acc[mi][ni], afh[mi], bfl[ni]);
                    mma16816(acc[mi][ni], afl[mi], bfh[ni]);
                }
        }
        __syncthreads();
    }

#pragma unroll
    for (int mi = 0; mi < 2; mi++) {
#pragma unroll
        for (int half = 0; half < 2; half++) {
            int m = m0 + warp_m * 32 + mi * 16 + r0 + half * 8;
            float* op = Out + (size_t)m * ND;
#pragma unroll
            for (int ni = 0; ni < 4; ni++) {
                int n = n0 + warp_n * 32 + ni * 8 + c0;
                float2 bb = *(const float2*)(bo + n);
                *(float2*)(op + n) =
                    make_float2(acc[mi][ni][half * 2] + bb.x,
                                acc[mi][ni][half * 2 + 1] + bb.y);
            }
        }
    }
}

// ---------------------------------------------------------------------------
// Causal flash attention, fp32 (R3-verified math); epilogue emits bf16 hi/lo ctx
// ---------------------------------------------------------------------------
__global__ __launch_bounds__(256)
void attn_kernel() {
    __shared__ float QsT[64][64];
    __shared__ float KP[64][64];
    __shared__ float Vs[64][64];

    const int bh = blockIdx.y;
    const int qb = (NT / 64 - 1) - blockIdx.x;
    const float* Qp = g_q + (size_t)bh * NT * NHD;
    const float* Kp = g_k + (size_t)bh * NT * NHD;
    const float* Vp = g_v + (size_t)bh * NT * NHD;

    const int t = threadIdx.x;
    const int tx = t & 15, ty = t >> 4;
    const int r = t >> 2, c = t & 3;

#pragma unroll
    for (int w = 0; w < 4; w++) {
        float4 qv = *(const float4*)(Qp + (size_t)(qb * 64 + r) * NHD + 16 * w + 4 * c);
        QsT[16 * w + 4 * c + 0][r] = qv.x;
        QsT[16 * w + 4 * c + 1][r] = qv.y;
        QsT[16 * w + 4 * c + 2][r] = qv.z;
        QsT[16 * w + 4 * c + 3][r] = qv.w;
    }

    float Oacc[4][4] = {};
    float mrow[4] = {-1e30f, -1e30f, -1e30f, -1e30f};
    float lrow[4] = {};

    for (int kb = 0; kb <= qb; kb++) {
        __syncthreads();
#pragma unroll
        for (int w = 0; w < 4; w++) {
            float4 kv = *(const float4*)(Kp + (size_t)(kb * 64 + r) * NHD + 16 * w + 4 * c);
            KP[16 * w + 4 * c + 0][r] = kv.x;
            KP[16 * w + 4 * c + 1][r] = kv.y;
            KP[16 * w + 4 * c + 2][r] = kv.z;
            KP[16 * w + 4 * c + 3][r] = kv.w;
        }
#pragma unroll
        for (int w = 0; w < 4; w++) {
            int idx = (w << 8) + t;
            int jr = idx >> 4, c4 = idx & 15;
            *(float4*)&Vs[jr][4 * c4] =
                *(const float4*)(Vp + (size_t)(kb * 64 + jr) * NHD + 4 * c4);
        }
        __syncthreads();

        float S[4][4] = {};
#pragma unroll 4
        for (int e = 0; e < 64; e++) {
            float4 a = *(const float4*)&QsT[e][4 * ty];
            float4 b = *(const float4*)&KP[e][4 * tx];
            float aa[4] = {a.x, a.y, a.z, a.w};
            float bb[4] = {b.x, b.y, b.z, b.w};
#pragma unroll
            for (int i = 0; i < 4; i++)
#pragma unroll
                for (int j = 0; j < 4; j++)
                    S[i][j] += aa[i] * bb[j];
        }

        const float sc = 0.03125f;
        if (kb == qb) {
#pragma unroll
            for (int i = 0; i < 4; i++)
#pragma unroll
                for (int j = 0; j < 4; j++) {
                    S[i][j] *= sc;
                    if (4 * tx + j > 4 * ty + i) S[i][j] = -1e30f;
                }
        } else {
#pragma unroll
            for (int i = 0; i < 4; i++)
#pragma unroll
                for (int j = 0; j < 4; j++)
                    S[i][j] *= sc;
        }

        float alpha[4];
#pragma unroll
        for (int i = 0; i < 4; i++) {
            float v = fmaxf(fmaxf(S[i][0], S[i][1]), fmaxf(S[i][2], S[i][3]));
#pragma unroll
            for (int off = 1; off < 16; off <<= 1)
                v = fmaxf(v, __shfl_xor_sync(0xffffffffu, v, off));
            float mn = fmaxf(mrow[i], v);
            alpha[i] = __expf(mrow[i] - mn);
            mrow[i] = mn;
            float rs = 0.0f;
#pragma unroll
            for (int j = 0; j < 4; j++) {
                S[i][j] = __expf(S[i][j] - mn);
                rs += S[i][j];
            }
#pragma unroll
            for (int off = 1; off < 16; off <<= 1)
                rs += __shfl_xor_sync(0xffffffffu, rs, off);
            lrow[i] = lrow[i] * alpha[i] + rs;
#pragma unroll
            for (int j = 0; j < 4; j++) Oacc[i][j] *= alpha[i];
        }

        __syncthreads();
#pragma unroll
        for (int i = 0; i < 4; i++)
            *(float4*)&KP[4 * ty + i][4 * tx] =
                make_float4(S[i][0], S[i][1], S[i][2], S[i][3]);
        __syncthreads();

#pragma unroll 4
        for (int j = 0; j < 64; j++) {
            float4 bv = *(const float4*)&Vs[j][4 * tx];
            float bb[4] = {bv.x, bv.y, bv.z, bv.w};
#pragma unroll
            for (int i = 0; i < 4; i++) {
                float a = KP[4 * ty + i][j];
#pragma unroll
                for (int jj = 0; jj < 4; jj++)
                    Oacc[i][jj] += a * bb[jj];
            }
        }
    }

    // epilogue: normalize, split to bf16 hi/lo ctx (row m = b*NT+t, col h*64+e)
    const int b = bh >> 4, h = bh & 15;
#pragma unroll
    for (int i = 0; i < 4; i++) {
        float inv = 1.0f / lrow[i];
        int trow = qb * 64 + 4 * ty + i;
        size_t idx = (size_t)(b * NT + trow) * ND + h * NHD + 4 * tx;
        __align__(8) __nv_bfloat16 hv[4], lv[4];
#pragma unroll
        for (int j = 0; j < 4; j++) split1(Oacc[i][j] * inv, hv[j], lv[j]);
        *(uint2*)(g_ctxh + idx) = *(uint2*)hv;
        *(uint2*)(g_ctxl + idx) = *(uint2*)lv;
    }
}

// ---------------------------------------------------------------------------
extern "C" void kernel_launch(void* const* d_in, const int* in_sizes, int n_in,
                              void* d_out, int out_size)
{
    const float* X  = (const float*)d_in[0];
    const float* Wq = (const float*)d_in[1];
    const float* Wk = (const float*)d_in[2];
    const float* Wv = (const float*)d_in[3];
    const float* Wo = (const float*)d_in[4];
    const float* bo = (const float*)d_in[5];
    float* Out = (float*)d_out;

    split_x_kernel<<<NM * ND / 4 / 256, 256>>>(X);
    split_wo_kernel<<<ND * ND / 4 / 256, 256>>>(Wo);
    wsplit_kernel<<<dim3(ND / 64, NH, 3), 256>>>(Wq, Wk, Wv);

    qkv_tc_kernel<<<dim3(NM / 128, 3 * NH), 256>>>();
    attn_kernel<<<dim3(NT / 64, NB * NH), 256>>>();
    out_tc_kernel<<<dim3(NM / 128, ND / 64), 256>>>(bo, Out);
}